// round 16
// baseline (speedup 1.0000x reference)
#include <cuda_runtime.h>
#include <math.h>
#include <stdint.h>

#define HID 256
#define NLAYERS 15
#define MAXN 50000
#define MAXE 500000
#define EPS 1e-5f

typedef unsigned short u16;

// ---------------- scratch (static device globals) --------------------------
__device__ float g_h[(size_t)MAXN * HID];          // fp32 trunk
__device__ u16 g_hbf[(size_t)MAXN * HID];          // bf16 mirror (GEMM/gather)
__device__ u16 g_aggbf[(size_t)MAXN * HID];        // bf16 aggregation
__device__ unsigned g_outp[(size_t)MAXN * HID / 2]; // bf16 pair layer output
__device__ float g_sum[NLAYERS * HID];
__device__ float g_sq[NLAYERS * HID];
// pre-converted bf16 weights
__device__ u16 g_wrel_bf[NLAYERS * HID * HID];
__device__ u16 g_wroot_bf[NLAYERS * HID * HID];
__device__ u16 g_w1bf[2 * HID * HID];
__device__ u16 g_w2bf[HID * HID];
// CSR scratch
__device__ int g_cnt[MAXN];
__device__ int g_rowptr[MAXN + 1];
__device__ int g_cur[MAXN];
__device__ int g_csr[MAXE];

// fp32 -> bf16 bits, round-to-nearest-even
__device__ __forceinline__ u16 f2bf(float f) {
    unsigned u = __float_as_uint(f);
    u += 0x7fffu + ((u >> 16) & 1u);
    return (u16)(u >> 16);
}
__device__ __forceinline__ unsigned pack2(float lo, float hi) {
    return (unsigned)f2bf(lo) | ((unsigned)f2bf(hi) << 16);
}
__device__ __forceinline__ float bflo(unsigned p) {
    return __uint_as_float(p << 16);
}
__device__ __forceinline__ float bfhi(unsigned p) {
    return __uint_as_float(p & 0xffff0000u);
}

// ---------------- weight prep + stat zeroing -------------------------------
__global__ void k_prep(const float* __restrict__ Wrel,
                       const float* __restrict__ Wroot,
                       const float* __restrict__ W1,
                       const float* __restrict__ W2) {
    int i = blockIdx.x * 256 + threadIdx.x;
    const int NW = NLAYERS * HID * HID;
    if (i < NW) {
        g_wrel_bf[i] = f2bf(Wrel[i]);
        g_wroot_bf[i] = f2bf(Wroot[i]);
    }
    if (i < 2 * HID * HID) g_w1bf[i] = f2bf(W1[i]);
    if (i < HID * HID) g_w2bf[i] = f2bf(W2[i]);
    if (i < NLAYERS * HID) {
        g_sum[i] = 0.f;
        g_sq[i] = 0.f;
    }
}

// ---------------- input fc: h = x @ W_in^T (IN_CH=2) -----------------------
__global__ void k_input(const float* __restrict__ x,
                        const float* __restrict__ Win, int N) {
    int i = blockIdx.x;
    int j = threadIdx.x;
    if (i < N) {
        float v = fmaf(x[2 * i], Win[2 * j], x[2 * i + 1] * Win[2 * j + 1]);
        size_t idx = (size_t)i * HID + j;
        g_h[idx] = v;
        g_hbf[idx] = f2bf(v);
    }
}

// ---------------- CSR build ------------------------------------------------
__global__ void k_zero_cnt(int N) {
    int i = blockIdx.x * blockDim.x + threadIdx.x;
    if (i < N) g_cnt[i] = 0;
}
__global__ void k_hist(const int* __restrict__ ei, int E) {
    int e = blockIdx.x * blockDim.x + threadIdx.x;
    if (e < E) atomicAdd(&g_cnt[ei[E + e]], 1);
}
__global__ void k_scan(int N) {
    __shared__ int s[1024];
    int t = threadIdx.x;
    int chunk = (N + 1023) / 1024;
    int lo = t * chunk, hi = min(lo + chunk, N);
    int sum = 0;
    for (int i = lo; i < hi; i++) sum += g_cnt[i];
    s[t] = sum;
    __syncthreads();
    for (int off = 1; off < 1024; off <<= 1) {
        int v = (t >= off) ? s[t - off] : 0;
        __syncthreads();
        s[t] += v;
        __syncthreads();
    }
    int run = (t == 0) ? 0 : s[t - 1];
    for (int i = lo; i < hi; i++) {
        g_rowptr[i] = run;
        g_cur[i] = run;
        run += g_cnt[i];
    }
    if (t == 0) g_rowptr[N] = s[1023];
}
__global__ void k_fill(const int* __restrict__ ei, int E) {
    int e = blockIdx.x * blockDim.x + threadIdx.x;
    if (e < E) {
        int d = ei[E + e];
        int p = atomicAdd(&g_cur[d], 1);
        g_csr[p] = ei[e];
    }
}

// ------- CSR aggregate: bf16 gather, fp32 accum, bf16 out ------------------
// warp per node; 8 indices fetched coalesced + broadcast, then 8 INDEPENDENT
// row loads issued back-to-back (MLP 8) before accumulation. Accumulation
// order over edges is unchanged (CSR order).
__global__ void __launch_bounds__(256) k_aggr(int N) {
    int node = blockIdx.x * 8 + (threadIdx.x >> 5);
    int lane = threadIdx.x & 31;
    if (node >= N) return;
    int s = g_rowptr[node], e = g_rowptr[node + 1];
    float acc[8] = {};
    for (int base = s; base < e; base += 8) {
        int nb = e - base;
        nb = (nb > 8) ? 8 : nb;
        int idx = (lane < nb) ? g_csr[base + lane] : 0;
        uint4 v[8];
#pragma unroll
        for (int j = 0; j < 8; j++) {
            int src = __shfl_sync(0xffffffffu, idx, j);
            if (j < nb)
                v[j] = *reinterpret_cast<const uint4*>(
                    g_hbf + (size_t)src * HID + lane * 8);
        }
#pragma unroll
        for (int j = 0; j < 8; j++) {
            if (j < nb) {
                acc[0] += bflo(v[j].x); acc[1] += bfhi(v[j].x);
                acc[2] += bflo(v[j].y); acc[3] += bfhi(v[j].y);
                acc[4] += bflo(v[j].z); acc[5] += bfhi(v[j].z);
                acc[6] += bflo(v[j].w); acc[7] += bfhi(v[j].w);
            }
        }
    }
    uint4 o;
    o.x = pack2(acc[0], acc[1]);
    o.y = pack2(acc[2], acc[3]);
    o.z = pack2(acc[4], acc[5]);
    o.w = pack2(acc[6], acc[7]);
    *reinterpret_cast<uint4*>(g_aggbf + (size_t)node * HID + lane * 8) = o;
}

// ================= bf16 m16n8k16 tensor-core GEMM machinery ================
#define BM 128
#define BN 128
#define BK 32          // bf16 K per stage
#define NSW 20         // smem row stride in 32-bit words (= 40 bf16, pad 8)
#define TSW (128 * NSW)

__device__ __forceinline__ void mma16(float* c, const unsigned* a,
                                      const unsigned* b) {
    asm volatile(
        "mma.sync.aligned.m16n8k16.row.col.f32.bf16.bf16.f32 "
        "{%0,%1,%2,%3}, {%4,%5,%6,%7}, {%8,%9}, {%0,%1,%2,%3};"
        : "+f"(c[0]), "+f"(c[1]), "+f"(c[2]), "+f"(c[3])
        : "r"(a[0]), "r"(a[1]), "r"(a[2]), "r"(a[3]), "r"(b[0]), "r"(b[1]));
}

// cp.async a 128x32 bf16 tile (row clamped): 256 threads, 32B per thread
__device__ __forceinline__ void async_tile(const u16* __restrict__ src,
                                           int row0, int maxrow, int ldk,
                                           int kbase, unsigned* sbuf,
                                           int tid) {
    int r = tid >> 1;
    int gr = min(row0 + r, maxrow - 1);
    const u16* p = src + (size_t)gr * ldk + kbase + (tid & 1) * 16;
    unsigned sa = (unsigned)__cvta_generic_to_shared(
        sbuf + r * NSW + (tid & 1) * 8);
    asm volatile("cp.async.ca.shared.global [%0], [%1], 16;"
                 :: "r"(sa), "l"(p));
    asm volatile("cp.async.ca.shared.global [%0], [%1], 16;"
                 :: "r"(sa + 16), "l"(p + 8));
}

// cp.async a (256 x 32) bf16 tile with 512 threads (2 threads/row)
__device__ __forceinline__ void async_tile512(const u16* __restrict__ src,
                                              int ldk, int kbase,
                                              unsigned* sbuf, int tid) {
    int r = tid >> 1;
    const u16* p = src + (size_t)r * ldk + kbase + (tid & 1) * 16;
    unsigned sa = (unsigned)__cvta_generic_to_shared(
        sbuf + r * NSW + (tid & 1) * 8);
    asm volatile("cp.async.ca.shared.global [%0], [%1], 16;"
                 :: "r"(sa), "l"(p));
    asm volatile("cp.async.ca.shared.global [%0], [%1], 16;"
                 :: "r"(sa + 16), "l"(p + 8));
}

// one BK=32 stage, 8-warp (2x4) layout, warp tile 64x32
__device__ __forceinline__ void stage_mma(const unsigned* sA,
                                          const unsigned* sB, int wm, int wn,
                                          int lane, float acc[4][4][4]) {
#pragma unroll
    for (int ks = 0; ks < 2; ks++) {
        unsigned a[4][4], b[4][2];
        int co = ks * 8 + (lane & 3);
#pragma unroll
        for (int mt = 0; mt < 4; mt++) {
            int row = wm * 64 + mt * 16 + (lane >> 2);
            const unsigned* p = sA + row * NSW + co;
            a[mt][0] = p[0];
            a[mt][1] = p[8 * NSW];
            a[mt][2] = p[4];
            a[mt][3] = p[8 * NSW + 4];
        }
#pragma unroll
        for (int nt = 0; nt < 4; nt++) {
            int n = wn * 32 + nt * 8 + (lane >> 2);
            const unsigned* p = sB + n * NSW + co;
            b[nt][0] = p[0];
            b[nt][1] = p[4];
        }
#pragma unroll
        for (int mt = 0; mt < 4; mt++)
#pragma unroll
            for (int nt = 0; nt < 4; nt++)
                mma16(acc[mt][nt], a[mt], b[nt]);
    }
}

// ---------- node layer: g_out = agg @ Wrel^T + h @ Wroot^T + brel ----------
// 3-stage cp.async ring, ONE barrier per K-stage; epilogue fuses BN stats and
// writes g_out as bf16 pairs (stats from fp32 pre-rounding values).
__global__ void __launch_bounds__(256, 2)
k_gemm_node(int l, const float* __restrict__ brel, int M) {
    extern __shared__ unsigned dsm[];
    unsigned* sA = dsm;               // 3 bufs x 128x20 words
    unsigned* sB = dsm + 3 * TSW;     // 3 bufs x 128x20 words

    int tid = threadIdx.x, lane = tid & 31, wid = tid >> 5;
    int wm = wid >> 2, wn = wid & 3;
    int bm = blockIdx.y * BM, bn = blockIdx.x * BN;

    const u16* Wr = g_wrel_bf + (size_t)l * HID * HID;
    const u16* Wo = g_wroot_bf + (size_t)l * HID * HID;

    float acc[4][4][4] = {};

#define PRODUCE(s, buf)                                                     \
    {                                                                       \
        int seg = (s) >> 3, k0 = ((s) & 7) * BK;                            \
        const u16* A = seg ? g_hbf : g_aggbf;                               \
        const u16* W = seg ? Wo : Wr;                                       \
        async_tile(A, bm, M, HID, k0, sA + (buf) * TSW, tid);               \
        async_tile(W, bn, HID, HID, k0, sB + (buf) * TSW, tid);             \
    }

    PRODUCE(0, 0);
    asm volatile("cp.async.commit_group;");
    PRODUCE(1, 1);
    asm volatile("cp.async.commit_group;");
#pragma unroll 1
    for (int s = 0; s < 16; s++) {
        asm volatile("cp.async.wait_group 1;");
        __syncthreads();
        int cur = s - (s / 3) * 3;           // s % 3
        stage_mma(sA + cur * TSW, sB + cur * TSW, wm, wn, lane, acc);
        if (s + 2 < 16) {
            int nxt = (s + 2) - ((s + 2) / 3) * 3;
            PRODUCE(s + 2, nxt);
        }
        asm volatile("cp.async.commit_group;");
    }
#undef PRODUCE

    // write (bf16 pairs) + fused BN statistics (fp32, pre-rounding)
    float* gsum = g_sum + l * HID;
    float* gsq = g_sq + l * HID;
#pragma unroll
    for (int nt = 0; nt < 4; nt++) {
        int c = bn + wn * 32 + nt * 8 + 2 * (lane & 3);
        float b0 = brel[c], b1 = brel[c + 1];
        float s0 = 0.f, s1 = 0.f, q0 = 0.f, q1 = 0.f;
#pragma unroll
        for (int mt = 0; mt < 4; mt++) {
            int r0 = bm + wm * 64 + mt * 16 + (lane >> 2);
            if (r0 < M) {
                float v0 = acc[mt][nt][0] + b0;
                float v1 = acc[mt][nt][1] + b1;
                g_outp[(size_t)r0 * (HID / 2) + (c >> 1)] = pack2(v0, v1);
                s0 += v0; q0 = fmaf(v0, v0, q0);
                s1 += v1; q1 = fmaf(v1, v1, q1);
            }
            if (r0 + 8 < M) {
                float v0 = acc[mt][nt][2] + b0;
                float v1 = acc[mt][nt][3] + b1;
                g_outp[(size_t)(r0 + 8) * (HID / 2) + (c >> 1)] = pack2(v0, v1);
                s0 += v0; q0 = fmaf(v0, v0, q0);
                s1 += v1; q1 = fmaf(v1, v1, q1);
            }
        }
#pragma unroll
        for (int off = 4; off < 32; off <<= 1) {
            s0 += __shfl_xor_sync(0xffffffffu, s0, off);
            s1 += __shfl_xor_sync(0xffffffffu, s1, off);
            q0 += __shfl_xor_sync(0xffffffffu, q0, off);
            q1 += __shfl_xor_sync(0xffffffffu, q1, off);
        }
        if (lane < 4) {
            atomicAdd(&gsum[c], s0);
            atomicAdd(&gsum[c + 1], s1);
            atomicAdd(&gsq[c], q0);
            atomicAdd(&gsq[c + 1], q1);
        }
    }
}

// ---------------- BN apply (bf16 g_out pairs, 16 rows/block) ---------------
__global__ void __launch_bounds__(256) k_bn_apply(const float* __restrict__ gamma,
                                                  const float* __restrict__ beta,
                                                  float invN, int N, int l) {
    int tid = threadIdx.x;
    int cp = tid & 127;       // column pair index
    int half = tid >> 7;      // 0 or 1
    int c = cp * 2;
    float m0 = g_sum[l * HID + c] * invN;
    float m1 = g_sum[l * HID + c + 1] * invN;
    float v0 = g_sq[l * HID + c] * invN - m0 * m0;
    float v1 = g_sq[l * HID + c + 1] * invN - m1 * m1;
    float sc0 = rsqrtf(v0 + EPS) * gamma[c];
    float sc1 = rsqrtf(v1 + EPS) * gamma[c + 1];
    float sh0 = beta[c] - m0 * sc0;
    float sh1 = beta[c + 1] - m1 * sc1;

    unsigned* hbfp = reinterpret_cast<unsigned*>(g_hbf);
    int r0 = blockIdx.x * 16 + half * 8;
    int r1 = min(r0 + 8, N);
    for (int r = r0; r < r1; r++) {
        unsigned p = g_outp[(size_t)r * 128 + cp];
        float o0 = fmaf(bflo(p), sc0, sh0);
        float o1 = fmaf(bfhi(p), sc1, sh1);
        float2 h = *reinterpret_cast<float2*>(g_h + (size_t)r * HID + c);
        h.x += fmaxf(o0, 0.f);
        h.y += fmaxf(o1, 0.f);
        *reinterpret_cast<float2*>(g_h + (size_t)r * HID + c) = h;
        hbfp[(size_t)r * 128 + cp] = pack2(h.x, h.y);
    }
}

// ================= fused edge MLP ==========================================
#define ETM 128
#define Z1W 132   // z1 smem row stride in words (= 264 bf16); conflict-free

// 16-warp (4x4) stage: warp tile 32x64
__device__ __forceinline__ void stage_mma16e(const unsigned* sA, int ldA,
                                             int kw0, const unsigned* sB,
                                             int wm, int wn, int lane,
                                             float acc[2][8][4]) {
#pragma unroll
    for (int ks = 0; ks < 2; ks++) {
        unsigned a[2][4], b[8][2];
        int coA = kw0 + ks * 8 + (lane & 3);
        int coB = ks * 8 + (lane & 3);
#pragma unroll
        for (int mt = 0; mt < 2; mt++) {
            int row = wm * 32 + mt * 16 + (lane >> 2);
            const unsigned* p = sA + row * ldA + coA;
            a[mt][0] = p[0];
            a[mt][1] = p[8 * ldA];
            a[mt][2] = p[4];
            a[mt][3] = p[8 * ldA + 4];
        }
#pragma unroll
        for (int nt = 0; nt < 8; nt++) {
            int n = wn * 64 + nt * 8 + (lane >> 2);
            const unsigned* p = sB + n * NSW + coB;
            b[nt][0] = p[0];
            b[nt][1] = p[4];
        }
#pragma unroll
        for (int mt = 0; mt < 2; mt++)
#pragma unroll
            for (int nt = 0; nt < 8; nt++)
                mma16(acc[mt][nt], a[mt], b[nt]);
    }
}

__global__ void __launch_bounds__(512, 1)
k_edge_fused(const int* __restrict__ ei, int E,
             const float* __restrict__ b1, const float* __restrict__ b2,
             const float* __restrict__ W3, const float* __restrict__ b3,
             float* __restrict__ out) {
    extern __shared__ unsigned esm[];
    unsigned* sA = esm;                        // 128*20 words
    unsigned* sB = sA + ETM * NSW;             // 256*20 words
    unsigned* z1s = sB + 256 * NSW;            // 128*132 words
    float* sdot = (float*)(z1s + ETM * Z1W);   // 128 floats

    int tid = threadIdx.x, lane = tid & 31, wid = tid >> 5;
    int wm = wid >> 2, wn = wid & 3;
    int bm = blockIdx.x * ETM;

    if (tid < ETM) sdot[tid] = 0.f;

    int e = min(bm + (tid >> 2), E - 1);
    int nsrc = ei[e], ndst = ei[E + e];

    float acc[2][8][4] = {};

    // ---- stage 1: z1 = relu(cat(h[src],h[dst]) @ W1^T + b1), K = 512 ------
#pragma unroll 1
    for (int k0 = 0; k0 < 2 * HID; k0 += BK) {
        {
            // gather: cp.async 16B per thread from h rows
            int kg = k0 + (tid & 3) * 8;
            int node = (kg < HID) ? nsrc : ndst;
            const u16* p = g_hbf + (size_t)node * HID + (kg & (HID - 1));
            unsigned sa = (unsigned)__cvta_generic_to_shared(
                sA + (tid >> 2) * NSW + (tid & 3) * 4);
            asm volatile("cp.async.ca.shared.global [%0], [%1], 16;"
                         :: "r"(sa), "l"(p));
        }
        async_tile512(g_w1bf, 2 * HID, k0, sB, tid);
        asm volatile("cp.async.commit_group;");
        asm volatile("cp.async.wait_group 0;");
        __syncthreads();
        stage_mma16e(sA, NSW, 0, sB, wm, wn, lane, acc);
        __syncthreads();
    }

    // store z1 (bias+relu, bf16 pairs) into smem; zero acc for stage 2
#pragma unroll
    for (int mt = 0; mt < 2; mt++) {
        int r0 = wm * 32 + mt * 16 + (lane >> 2);
#pragma unroll
        for (int nt = 0; nt < 8; nt++) {
            int c = wn * 64 + nt * 8 + 2 * (lane & 3);
            float bb0 = b1[c], bb1 = b1[c + 1];
            z1s[r0 * Z1W + (c >> 1)] =
                pack2(fmaxf(acc[mt][nt][0] + bb0, 0.f),
                      fmaxf(acc[mt][nt][1] + bb1, 0.f));
            z1s[(r0 + 8) * Z1W + (c >> 1)] =
                pack2(fmaxf(acc[mt][nt][2] + bb0, 0.f),
                      fmaxf(acc[mt][nt][3] + bb1, 0.f));
#pragma unroll
            for (int q = 0; q < 4; q++) acc[mt][nt][q] = 0.f;
        }
    }

    // ---- stage 2: z2 = relu(z1 @ W2^T + b2), K = 256, A from smem ---------
#pragma unroll 1
    for (int k0 = 0; k0 < HID; k0 += BK) {
        async_tile512(g_w2bf, HID, k0, sB, tid);
        asm volatile("cp.async.commit_group;");
        asm volatile("cp.async.wait_group 0;");
        __syncthreads();
        stage_mma16e(z1s, Z1W, k0 >> 1, sB, wm, wn, lane, acc);
        __syncthreads();
    }

    // ---- stage 3: per-edge dot with W3 + sigmoid --------------------------
    float part[2][2] = {};
#pragma unroll
    for (int mt = 0; mt < 2; mt++) {
#pragma unroll
        for (int nt = 0; nt < 8; nt++) {
            int c = wn * 64 + nt * 8 + 2 * (lane & 3);
            float bb0 = b2[c], bb1 = b2[c + 1];
            float w0 = W3[c], w1 = W3[c + 1];
            float z0 = fmaxf(acc[mt][nt][0] + bb0, 0.f);
            float z1v = fmaxf(acc[mt][nt][1] + bb1, 0.f);
            float z2v = fmaxf(acc[mt][nt][2] + bb0, 0.f);
            float z3 = fmaxf(acc[mt][nt][3] + bb1, 0.f);
            part[mt][0] = fmaf(z0, w0, fmaf(z1v, w1, part[mt][0]));
            part[mt][1] = fmaf(z2v, w0, fmaf(z3, w1, part[mt][1]));
        }
    }
#pragma unroll
    for (int off = 1; off < 4; off <<= 1) {
        part[0][0] += __shfl_xor_sync(0xffffffffu, part[0][0], off);
        part[0][1] += __shfl_xor_sync(0xffffffffu, part[0][1], off);
        part[1][0] += __shfl_xor_sync(0xffffffffu, part[1][0], off);
        part[1][1] += __shfl_xor_sync(0xffffffffu, part[1][1], off);
    }
    if ((lane & 3) == 0) {
#pragma unroll
        for (int mt = 0; mt < 2; mt++) {
            int r0 = wm * 32 + mt * 16 + (lane >> 2);
            atomicAdd(&sdot[r0], part[mt][0]);
            atomicAdd(&sdot[r0 + 8], part[mt][1]);
        }
    }
    __syncthreads();
    if (tid < ETM) {
        int eo = bm + tid;
        if (eo < E)
            out[eo] = 1.f / (1.f + expf(-(sdot[tid] + b3[0])));
    }
}

// ---------------- host orchestration ---------------------------------------
extern "C" void kernel_launch(void* const* d_in, const int* in_sizes, int n_in,
                              void* d_out, int out_size) {
    const float* x     = (const float*)d_in[0];
    const int*   ei    = (const int*)d_in[1];
    const float* Win   = (const float*)d_in[2];
    const float* Wrel  = (const float*)d_in[3];
    const float* brel  = (const float*)d_in[4];
    const float* Wroot = (const float*)d_in[5];
    const float* gamma = (const float*)d_in[6];
    const float* beta  = (const float*)d_in[7];
    const float* W1    = (const float*)d_in[8];
    const float* b1    = (const float*)d_in[9];
    const float* W2    = (const float*)d_in[10];
    const float* b2    = (const float*)d_in[11];
    const float* W3    = (const float*)d_in[12];
    const float* b3    = (const float*)d_in[13];

    int N = in_sizes[0] / 2;
    int E = in_sizes[1] / 2;
    float* out = (float*)d_out;

    const size_t gsmem = 6 * (size_t)TSW * 4;                 // 61440 B
    const size_t esmem =
        (ETM * NSW + 256 * NSW + (size_t)ETM * Z1W) * 4 + ETM * 4;  // 98816 B
    cudaFuncSetAttribute(k_gemm_node,
                         cudaFuncAttributeMaxDynamicSharedMemorySize,
                         (int)gsmem);
    cudaFuncSetAttribute(k_edge_fused,
                         cudaFuncAttributeMaxDynamicSharedMemorySize,
                         (int)esmem);

    // CSR build + weight prep + stat zeroing
    k_zero_cnt<<<(N + 255) / 256, 256>>>(N);
    k_hist<<<(E + 255) / 256, 256>>>(ei, E);
    k_scan<<<1, 1024>>>(N);
    k_fill<<<(E + 255) / 256, 256>>>(ei, E);
    k_prep<<<(NLAYERS * HID * HID + 255) / 256, 256>>>(Wrel, Wroot, W1, W2);

    k_input<<<N, HID>>>(x, Win, N);

    dim3 gN(HID / BN, (N + BM - 1) / BM);

    for (int l = 0; l < NLAYERS; l++) {
        k_aggr<<<(N + 7) / 8, 256>>>(N);
        k_gemm_node<<<gN, 256, gsmem>>>(l, brel + (size_t)l * HID, N);
        k_bn_apply<<<(N + 15) / 16, 256>>>(gamma + (size_t)l * HID,
                                           beta + (size_t)l * HID,
                                           1.0f / (float)N, N, l);
    }

    k_edge_fused<<<(E + ETM - 1) / ETM, 512, esmem>>>(ei, E, b1, b2, W3, b3,
                                                      out);
}